// round 3
// baseline (speedup 1.0000x reference)
#include <cuda_runtime.h>

#define BB 2
#define MM 4
#define CCH 64
#define VV 110592
#define KK 4
#define CB 4            // channels per block
#define CG 16           // channel groups
#define VS 12           // V splits
#define VCHUNK (VV/VS)  // 9216 -> 9 iters of 1024
#define NBLK (BB*MM*CG*VS)  // 1536
#define EPSL 1e-6f

// ---- scratch (no allocations allowed) ----
__device__ float g_numpart[NBLK * CB * KK];     // per-block (cc,k) partials
__device__ float g_twpart[BB*MM*VS*KK];         // (bm, vs, k)
__device__ float g_cntpart[BB*VS*KK];           // (b, vs, k)
__device__ unsigned g_ctr;                      // zero-init; reset each launch

__global__ __launch_bounds__(256, 3) void kmain(const float* __restrict__ f,
                                                const float* __restrict__ w,
                                                const int*   __restrict__ tw_words,
                                                float* __restrict__ out) {
    const int bm = blockIdx.x;   // 0..7 (b*4+m)
    const int cg = blockIdx.y;   // 0..15
    const int vs = blockIdx.z;   // 0..11
    const int b  = bm >> 2;
    const int tid = threadIdx.x;
    const int lane = tid & 31, wid = tid >> 5;

    __shared__ float sred[8][16];
    __shared__ float s_proto[2048];
    __shared__ float s_tw[32];
    __shared__ float s_cnt[8];
    __shared__ float s_aterm[48], s_acnt[48], s_sterm[48], s_scnt[48];
    __shared__ int   s_last;

    // ---- dtype detect: every block scans the SAME first 2048 high-words ----
    int any = 0;
    for (int i = tid; i < 2048; i += 256) any |= tw_words[2*i + 1];
    const int is64 = (__syncthreads_or(any) == 0);

    const long vbase = (long)vs * VCHUNK;
    const float* fb = f + ((long)bm*CCH + (long)cg*CB)*VV + vbase;
    const float* wb = w + (long)bm*VV + vbase;
    const long  ebase = (long)b*VV + vbase;

    float acc[CB][KK];
#pragma unroll
    for (int cc = 0; cc < CB; cc++)
#pragma unroll
        for (int k = 0; k < KK; k++) acc[cc][k] = 0.f;
    float twl[KK] = {0.f,0.f,0.f,0.f};
    float cl [KK] = {0.f,0.f,0.f,0.f};
    const bool doTW  = (cg == 0);
    const bool doCNT = doTW && ((bm & 3) == 0);

#pragma unroll 1
    for (int i = 0; i < VCHUNK/1024; i++) {   // 9 iterations
        const int v = (i*256 + tid)*4;
        // --- batch all loads up front for MLP ---
        float4 wv = *(const float4*)(wb + v);
        int t0,t1,t2,t3;
        {
            long e = ebase + v;
            if (is64) {
                const int4* p = (const int4*)tw_words + (e >> 1);
                int4 q0 = p[0], q1 = p[1];
                t0 = q0.x; t1 = q0.z; t2 = q1.x; t3 = q1.z;
            } else {
                int4 q = ((const int4*)tw_words)[e >> 2];
                t0 = q.x; t1 = q.y; t2 = q.z; t3 = q.w;
            }
        }
        float4 fv[CB];
#pragma unroll
        for (int cc = 0; cc < CB; cc++)
            fv[cc] = *(const float4*)(fb + (long)cc*VV + v);

        const int   ts[4] = { t0, t1, t2, t3 };
        const float ws[4] = { wv.x, wv.y, wv.z, wv.w };
        float msk[4][KK];
#pragma unroll
        for (int j = 0; j < 4; j++)
#pragma unroll
            for (int k = 0; k < KK; k++)
                msk[j][k] = (ts[j] == k) ? ws[j] : 0.f;

        if (doTW) {
#pragma unroll
            for (int k = 0; k < KK; k++)
                twl[k] += (msk[0][k] + msk[1][k]) + (msk[2][k] + msk[3][k]);
        }
        if (doCNT) {
#pragma unroll
            for (int k = 0; k < KK; k++) {
                float c0 = (t0==k)?1.f:0.f, c1 = (t1==k)?1.f:0.f;
                float c2 = (t2==k)?1.f:0.f, c3 = (t3==k)?1.f:0.f;
                cl[k] += (c0+c1)+(c2+c3);
            }
        }
#pragma unroll
        for (int cc = 0; cc < CB; cc++) {
            const float fs[4] = { fv[cc].x, fv[cc].y, fv[cc].z, fv[cc].w };
#pragma unroll
            for (int k = 0; k < KK; k++) {
                acc[cc][k] += fs[0]*msk[0][k];
                acc[cc][k] += fs[1]*msk[1][k];
                acc[cc][k] += fs[2]*msk[2][k];
                acc[cc][k] += fs[3]*msk[3][k];
            }
        }
    }

    // ---- block-reduce 16 accumulators ----
#pragma unroll
    for (int cc = 0; cc < CB; cc++)
#pragma unroll
        for (int k = 0; k < KK; k++)
#pragma unroll
            for (int off = 16; off > 0; off >>= 1)
                acc[cc][k] += __shfl_down_sync(0xffffffffu, acc[cc][k], off);
    if (lane == 0) {
#pragma unroll
        for (int cc = 0; cc < CB; cc++)
#pragma unroll
            for (int k = 0; k < KK; k++) sred[wid][cc*KK + k] = acc[cc][k];
    }
    __syncthreads();
    const int bid = (bm*CG + cg)*VS + vs;
    if (tid < 16) {
        float s = 0.f;
#pragma unroll
        for (int ww = 0; ww < 8; ww++) s += sred[ww][tid];
        g_numpart[bid*16 + tid] = s;
    }
    __syncthreads();

    // ---- block-reduce tw/cnt (8 values) ----
    {
        float vals[8];
#pragma unroll
        for (int j = 0; j < 4; j++) { vals[j] = twl[j]; vals[4+j] = cl[j]; }
#pragma unroll
        for (int j = 0; j < 8; j++)
#pragma unroll
            for (int off = 16; off > 0; off >>= 1)
                vals[j] += __shfl_down_sync(0xffffffffu, vals[j], off);
        if (lane == 0) {
#pragma unroll
            for (int j = 0; j < 8; j++) sred[wid][j] = vals[j];
        }
        __syncthreads();
        if (tid < 8) {
            float s = 0.f;
#pragma unroll
            for (int ww = 0; ww < 8; ww++) s += sred[ww][tid];
            if (tid < 4) {
                if (doTW) g_twpart[(bm*VS + vs)*4 + tid] = s;
            } else {
                if (doCNT) g_cntpart[(b*VS + vs)*4 + (tid-4)] = s;
            }
        }
    }

    // ---- last-block-done finalize ----
    __threadfence();
    __syncthreads();
    if (tid == 0) {
        unsigned old = atomicAdd(&g_ctr, 1u);
        s_last = (old == (unsigned)(NBLK - 1));
    }
    __syncthreads();
    if (!s_last) return;

    // Phase A: tw (32) + cnt (8)
    if (tid < 32) {
        int bm_ = tid >> 2, k = tid & 3;
        float s = 0.f;
        for (int v = 0; v < VS; v++) s += g_twpart[(bm_*VS + v)*4 + k];
        s_tw[tid] = s + EPSL;
    } else if (tid < 40) {
        int j = tid - 32, b_ = j >> 2, k = j & 3;
        float s = 0.f;
        for (int v = 0; v < VS; v++) s += g_cntpart[(b_*VS + v)*4 + k];
        s_cnt[j] = s;
    }
    __syncthreads();

    // Phase B: proto raw = num / tw
    for (int cell = tid; cell < 2048; cell += 256) {
        int bm_ = cell >> 8;
        int rem = cell & 255;
        int c = rem >> 2, k = rem & 3;
        int cg_ = c >> 2, cc = c & 3;
        float s = 0.f;
        for (int v = 0; v < VS; v++)
            s += g_numpart[((bm_*CG + cg_)*VS + v)*16 + cc*4 + k];
        s_proto[(bm_*4 + k)*64 + c] = s / s_tw[bm_*4 + k];
    }
    __syncthreads();

    // Phase C: normalize 32 rows (8 warps x 4 rows)
#pragma unroll
    for (int j = 0; j < 4; j++) {
        int r = wid + 8*j;
        float v1 = s_proto[r*64 + lane];
        float v2 = s_proto[r*64 + lane + 32];
        float ss = v1*v1 + v2*v2;
#pragma unroll
        for (int off = 16; off > 0; off >>= 1)
            ss += __shfl_xor_sync(0xffffffffu, ss, off);
        float norm = fmaxf(sqrtf(fmaxf(ss, 1e-24f)), 1e-12f);
        float inv = 1.f / norm;
        s_proto[r*64 + lane]      = v1 * inv;
        s_proto[r*64 + lane + 32] = v2 * inv;
    }
    __syncthreads();

    // Phase D: 96 pair dot products (8 warps x 12 pairs)
    {
        const int p1t[6] = {0,0,0,1,1,2};
        const int p2t[6] = {1,2,3,2,3,3};
        for (int p = wid; p < 96; p += 8) {
            int r1, r2, outidx;
            bool val;
            bool isAlign = (p < 48);
            float om = 1.f;
            if (isAlign) {
                int pa = p;
                int b_ = pa / 24; int rem = pa % 24;
                int mp = rem >> 2, k = rem & 3;
                int m = p1t[mp], n = p2t[mp];
                r1 = (b_*4 + m)*4 + k;
                r2 = (b_*4 + n)*4 + k;
                val = (s_cnt[b_*4 + k] >= 1.f) && (k != 0);
                float cd = s_cnt[b_*4 + k] + EPSL;
                om = (s_tw[r1] / cd) * (s_tw[r2] / cd);
                outidx = pa;
            } else {
                int ps = p - 48;
                int b_ = ps / 24; int rem = ps % 24;
                int m = rem / 6, kp = rem % 6;
                int k1 = p1t[kp], k2 = p2t[kp];
                r1 = (b_*4 + m)*4 + k1;
                r2 = (b_*4 + m)*4 + k2;
                val = (s_cnt[b_*4 + k1] >= 1.f) && (k1 != 0) &&
                      (s_cnt[b_*4 + k2] >= 1.f) && (k2 != 0);
                outidx = ps;
            }
            float a1 = s_proto[r1*64 + lane],      b1 = s_proto[r2*64 + lane];
            float a2 = s_proto[r1*64 + lane + 32], b2 = s_proto[r2*64 + lane + 32];
            float dot = a1*b1 + a2*b2;
#pragma unroll
            for (int off = 16; off > 0; off >>= 1)
                dot += __shfl_xor_sync(0xffffffffu, dot, off);
            if (lane == 0) {
                if (isAlign) {
                    s_aterm[outidx] = val ? om * fmaxf(0.9f - dot, 0.f) : 0.f;
                    s_acnt[outidx]  = val ? 1.f : 0.f;
                } else {
                    s_sterm[outidx] = val ? fmaxf(dot - 0.1f, 0.f) : 0.f;
                    s_scnt[outidx]  = val ? 1.f : 0.f;
                }
            }
        }
    }
    __syncthreads();

    // Phase E: scalar loss + counter reset
    if (tid == 0) {
        float as = 0.f, ac = 0.f, ssum = 0.f, sc = 0.f;
        for (int i = 0; i < 48; i++) { as += s_aterm[i]; ac += s_acnt[i]; }
        for (int i = 0; i < 48; i++) { ssum += s_sterm[i]; sc += s_scnt[i]; }
        out[0] = as / (ac + EPSL) + ssum / (sc + EPSL);
        g_ctr = 0;   // ready for next graph replay
    }
}

extern "C" void kernel_launch(void* const* d_in, const int* in_sizes, int n_in,
                              void* d_out, int out_size) {
    const float* feats   = (const float*)d_in[0];
    const float* weights = (const float*)d_in[1];
    const int*   tgt_w   = (const int*)d_in[2];   // int32 or int64; detected on-device
    float* out = (float*)d_out;

    kmain<<<dim3(BB*MM, CG, VS), 256>>>(feats, weights, tgt_w, out);
}

// round 4
// speedup vs baseline: 1.0090x; 1.0090x over previous
#include <cuda_runtime.h>
#include <cstdint>

#define BB 2
#define MM 4
#define CCH 64
#define VV 110592
#define KK 4
#define CB 8              // channels per block
#define CG 8              // channel groups
#define VS 12             // V splits
#define VCHUNK (VV/VS)    // 9216 elems
#define NST (VCHUNK/1024) // 9 stages of 1024 elems
#define NBLK (BB*MM*CG*VS)  // 768
#define EPSL 1e-6f

// dynamic smem stage layout (per stage, per block)
#define F_OFF 0
#define W_OFF 32768
#define T_OFF 36864
#define STAGE_BYTES 45056     // 32KB f + 4KB w + 8KB t(worst-case int64)
#define DYN_BYTES (2*STAGE_BYTES)

// ---- scratch (no allocations allowed) ----
__device__ float g_numpart[NBLK * 32];     // per-block (cc,k) partials
__device__ float g_twpart[BB*MM*VS*KK];    // (bm, vs, k)
__device__ float g_cntpart[BB*VS*KK];      // (b, vs, k)
__device__ unsigned g_ctr;                 // zero-init; reset each launch

#define CP16(dst, src) \
    asm volatile("cp.async.cg.shared.global [%0], [%1], 16;\n" :: "r"(dst), "l"(src) : "memory")

extern __shared__ char dynsm[];

__global__ __launch_bounds__(256, 2) void kmain(const float* __restrict__ f,
                                                const float* __restrict__ w,
                                                const int*   __restrict__ tw_words,
                                                float* __restrict__ out) {
    const int bm = blockIdx.x;   // 0..7 (b*4+m)
    const int cg = blockIdx.y;   // 0..7
    const int vs = blockIdx.z;   // 0..11
    const int b  = bm >> 2;
    const int tid = threadIdx.x;
    const int lane = tid & 31, wid = tid >> 5;

    __shared__ float sred[8][32];
    __shared__ float s_proto[2048];
    __shared__ float s_tw[32];
    __shared__ float s_cnt[8];
    __shared__ float s_aterm[48], s_acnt[48], s_sterm[48], s_scnt[48];
    __shared__ int   s_last;

    // ---- dtype detect: every block scans the SAME first 2048 high-words ----
    int any = 0;
    for (int i = tid; i < 2048; i += 256) any |= tw_words[2*i + 1];
    const int is64 = (__syncthreads_or(any) == 0);

    const long vbase = (long)vs * VCHUNK;
    const char* fsrc  = (const char*)(f + ((long)bm*CCH + (long)cg*CB)*VV + vbase) + (long)tid*16;
    const char* wsrc  = (const char*)(w + (long)bm*VV + vbase) + (long)tid*16;
    const char* tsrc32 = (const char*)tw_words + ((long)b*VV + vbase)*4 + (long)tid*16;
    const char* tsrc64 = (const char*)tw_words + ((long)b*VV + vbase)*8 + (long)tid*32;

    const uint32_t sm0 = (uint32_t)__cvta_generic_to_shared(dynsm);

    // issue stage s into slot s&1
#define ISSUE(s) do {                                                          \
        const int slot_ = (s) & 1;                                             \
        const uint32_t sb_ = sm0 + slot_*STAGE_BYTES;                          \
        const char* fs_ = fsrc + (long)(s)*4096;                               \
        _Pragma("unroll")                                                      \
        for (int cc_ = 0; cc_ < CB; cc_++)                                     \
            CP16(sb_ + F_OFF + cc_*4096 + tid*16, fs_ + (long)cc_*VV*4);       \
        CP16(sb_ + W_OFF + tid*16, wsrc + (long)(s)*4096);                     \
        if (is64) {                                                            \
            CP16(sb_ + T_OFF + tid*32,      tsrc64 + (long)(s)*8192);          \
            CP16(sb_ + T_OFF + tid*32 + 16, tsrc64 + (long)(s)*8192 + 16);     \
        } else {                                                               \
            CP16(sb_ + T_OFF + tid*16, tsrc32 + (long)(s)*4096);               \
        }                                                                      \
        asm volatile("cp.async.commit_group;\n" ::: "memory");                 \
    } while (0)

    float acc[CB][KK];
#pragma unroll
    for (int cc = 0; cc < CB; cc++)
#pragma unroll
        for (int k = 0; k < KK; k++) acc[cc][k] = 0.f;
    float twl[KK] = {0.f,0.f,0.f,0.f};
    float cl [KK] = {0.f,0.f,0.f,0.f};
    const bool doTW  = (cg == 0);
    const bool doCNT = doTW && ((bm & 3) == 0);

    ISSUE(0);
    ISSUE(1);

#pragma unroll 1
    for (int s = 0; s < NST; s++) {
        if (s < NST - 1) asm volatile("cp.async.wait_group 1;\n" ::: "memory");
        else             asm volatile("cp.async.wait_group 0;\n" ::: "memory");

        const int slot = s & 1;
        char* sb = dynsm + slot*STAGE_BYTES;

        float4 wv = *(const float4*)(sb + W_OFF + tid*16);
        int t0, t1, t2, t3;
        if (is64) {
            int4 qa = *(const int4*)(sb + T_OFF + tid*32);
            int4 qb = *(const int4*)(sb + T_OFF + tid*32 + 16);
            t0 = qa.x; t1 = qa.z; t2 = qb.x; t3 = qb.z;
        } else {
            int4 q = *(const int4*)(sb + T_OFF + tid*16);
            t0 = q.x; t1 = q.y; t2 = q.z; t3 = q.w;
        }

        const int   ts[4] = { t0, t1, t2, t3 };
        const float ws[4] = { wv.x, wv.y, wv.z, wv.w };
        float msk[4][KK];
#pragma unroll
        for (int j = 0; j < 4; j++)
#pragma unroll
            for (int k = 0; k < KK; k++)
                msk[j][k] = (ts[j] == k) ? ws[j] : 0.f;

        if (doTW) {
#pragma unroll
            for (int k = 0; k < KK; k++)
                twl[k] += (msk[0][k] + msk[1][k]) + (msk[2][k] + msk[3][k]);
        }
        if (doCNT) {
#pragma unroll
            for (int k = 0; k < KK; k++) {
                float c0 = (t0==k)?1.f:0.f, c1 = (t1==k)?1.f:0.f;
                float c2 = (t2==k)?1.f:0.f, c3 = (t3==k)?1.f:0.f;
                cl[k] += (c0+c1)+(c2+c3);
            }
        }

#pragma unroll
        for (int cc = 0; cc < CB; cc++) {
            float4 fv = *(const float4*)(sb + F_OFF + cc*4096 + tid*16);
            const float fs[4] = { fv.x, fv.y, fv.z, fv.w };
#pragma unroll
            for (int k = 0; k < KK; k++) {
                acc[cc][k] += fs[0]*msk[0][k];
                acc[cc][k] += fs[1]*msk[1][k];
                acc[cc][k] += fs[2]*msk[2][k];
                acc[cc][k] += fs[3]*msk[3][k];
            }
        }

        // issue next stage only AFTER this stage's smem values are consumed
        // (same thread, same addresses -> no WAR hazard, no __syncthreads needed)
        if (s + 2 < NST) ISSUE(s + 2);
    }

    // ---- block-reduce 32 accumulators ----
#pragma unroll
    for (int cc = 0; cc < CB; cc++)
#pragma unroll
        for (int k = 0; k < KK; k++)
#pragma unroll
            for (int off = 16; off > 0; off >>= 1)
                acc[cc][k] += __shfl_down_sync(0xffffffffu, acc[cc][k], off);
    if (lane == 0) {
#pragma unroll
        for (int cc = 0; cc < CB; cc++)
#pragma unroll
            for (int k = 0; k < KK; k++) sred[wid][cc*KK + k] = acc[cc][k];
    }
    __syncthreads();
    const int bid = (bm*CG + cg)*VS + vs;
    if (tid < 32) {
        float s = 0.f;
#pragma unroll
        for (int ww = 0; ww < 8; ww++) s += sred[ww][tid];
        g_numpart[bid*32 + tid] = s;
    }
    __syncthreads();

    // ---- block-reduce tw/cnt (8 values) ----
    {
        float vals[8];
#pragma unroll
        for (int j = 0; j < 4; j++) { vals[j] = twl[j]; vals[4+j] = cl[j]; }
#pragma unroll
        for (int j = 0; j < 8; j++)
#pragma unroll
            for (int off = 16; off > 0; off >>= 1)
                vals[j] += __shfl_down_sync(0xffffffffu, vals[j], off);
        if (lane == 0) {
#pragma unroll
            for (int j = 0; j < 8; j++) sred[wid][j] = vals[j];
        }
        __syncthreads();
        if (tid < 8) {
            float s = 0.f;
#pragma unroll
            for (int ww = 0; ww < 8; ww++) s += sred[ww][tid];
            if (tid < 4) {
                if (doTW) g_twpart[(bm*VS + vs)*4 + tid] = s;
            } else {
                if (doCNT) g_cntpart[(b*VS + vs)*4 + (tid-4)] = s;
            }
        }
    }

    // ---- last-block-done finalize ----
    __threadfence();
    __syncthreads();
    if (tid == 0) {
        unsigned old = atomicAdd(&g_ctr, 1u);
        s_last = (old == (unsigned)(NBLK - 1));
    }
    __syncthreads();
    if (!s_last) return;

    // Phase A: tw (32) + cnt (8)
    if (tid < 32) {
        int bm_ = tid >> 2, k = tid & 3;
        float s = 0.f;
        for (int v = 0; v < VS; v++) s += g_twpart[(bm_*VS + v)*4 + k];
        s_tw[tid] = s + EPSL;
    } else if (tid < 40) {
        int j = tid - 32, b_ = j >> 2, k = j & 3;
        float s = 0.f;
        for (int v = 0; v < VS; v++) s += g_cntpart[(b_*VS + v)*4 + k];
        s_cnt[j] = s;
    }
    __syncthreads();

    // Phase B: proto raw = num / tw
    for (int cell = tid; cell < 2048; cell += 256) {
        int bm_ = cell >> 8;
        int rem = cell & 255;
        int c = rem >> 2, k = rem & 3;
        int cg_ = c >> 3, cc = c & 7;
        float s = 0.f;
        for (int v = 0; v < VS; v++)
            s += g_numpart[((bm_*CG + cg_)*VS + v)*32 + cc*4 + k];
        s_proto[(bm_*4 + k)*64 + c] = s / s_tw[bm_*4 + k];
    }
    __syncthreads();

    // Phase C: normalize 32 rows (8 warps x 4 rows)
#pragma unroll
    for (int j = 0; j < 4; j++) {
        int r = wid + 8*j;
        float v1 = s_proto[r*64 + lane];
        float v2 = s_proto[r*64 + lane + 32];
        float ss = v1*v1 + v2*v2;
#pragma unroll
        for (int off = 16; off > 0; off >>= 1)
            ss += __shfl_xor_sync(0xffffffffu, ss, off);
        float norm = fmaxf(sqrtf(fmaxf(ss, 1e-24f)), 1e-12f);
        float inv = 1.f / norm;
        s_proto[r*64 + lane]      = v1 * inv;
        s_proto[r*64 + lane + 32] = v2 * inv;
    }
    __syncthreads();

    // Phase D: 96 pair dot products (8 warps x 12 pairs)
    {
        const int p1t[6] = {0,0,0,1,1,2};
        const int p2t[6] = {1,2,3,2,3,3};
        for (int p = wid; p < 96; p += 8) {
            int r1, r2, outidx;
            bool val;
            bool isAlign = (p < 48);
            float om = 1.f;
            if (isAlign) {
                int pa = p;
                int b_ = pa / 24; int rem = pa % 24;
                int mp = rem >> 2, k = rem & 3;
                int m = p1t[mp], n = p2t[mp];
                r1 = (b_*4 + m)*4 + k;
                r2 = (b_*4 + n)*4 + k;
                val = (s_cnt[b_*4 + k] >= 1.f) && (k != 0);
                float cd = s_cnt[b_*4 + k] + EPSL;
                om = (s_tw[r1] / cd) * (s_tw[r2] / cd);
                outidx = pa;
            } else {
                int ps = p - 48;
                int b_ = ps / 24; int rem = ps % 24;
                int m = rem / 6, kp = rem % 6;
                int k1 = p1t[kp], k2 = p2t[kp];
                r1 = (b_*4 + m)*4 + k1;
                r2 = (b_*4 + m)*4 + k2;
                val = (s_cnt[b_*4 + k1] >= 1.f) && (k1 != 0) &&
                      (s_cnt[b_*4 + k2] >= 1.f) && (k2 != 0);
                outidx = ps;
            }
            float a1 = s_proto[r1*64 + lane],      b1 = s_proto[r2*64 + lane];
            float a2 = s_proto[r1*64 + lane + 32], b2 = s_proto[r2*64 + lane + 32];
            float dot = a1*b1 + a2*b2;
#pragma unroll
            for (int off = 16; off > 0; off >>= 1)
                dot += __shfl_xor_sync(0xffffffffu, dot, off);
            if (lane == 0) {
                if (isAlign) {
                    s_aterm[outidx] = val ? om * fmaxf(0.9f - dot, 0.f) : 0.f;
                    s_acnt[outidx]  = val ? 1.f : 0.f;
                } else {
                    s_sterm[outidx] = val ? fmaxf(dot - 0.1f, 0.f) : 0.f;
                    s_scnt[outidx]  = val ? 1.f : 0.f;
                }
            }
        }
    }
    __syncthreads();

    // Phase E: scalar loss + counter reset
    if (tid == 0) {
        float as = 0.f, ac = 0.f, ssum = 0.f, sc = 0.f;
        for (int i = 0; i < 48; i++) { as += s_aterm[i]; ac += s_acnt[i]; }
        for (int i = 0; i < 48; i++) { ssum += s_sterm[i]; sc += s_scnt[i]; }
        out[0] = as / (ac + EPSL) + ssum / (sc + EPSL);
        g_ctr = 0;   // ready for next graph replay
    }
}

extern "C" void kernel_launch(void* const* d_in, const int* in_sizes, int n_in,
                              void* d_out, int out_size) {
    const float* feats   = (const float*)d_in[0];
    const float* weights = (const float*)d_in[1];
    const int*   tgt_w   = (const int*)d_in[2];   // int32 or int64; detected on-device
    float* out = (float*)d_out;

    cudaFuncSetAttribute(kmain, cudaFuncAttributeMaxDynamicSharedMemorySize, DYN_BYTES);
    kmain<<<dim3(BB*MM, CG, VS), 256, DYN_BYTES>>>(feats, weights, tgt_w, out);
}